// round 1
// baseline (speedup 1.0000x reference)
#include <cuda_runtime.h>

typedef unsigned long long u64;

#define NN 2048      // nodes
#define NE 6144      // edges
#define KDV 128      // DV_IN
#define DVO 64       // DV_OUT
#define DEI 16       // DE_IN
#define DEO 16       // DE_OUT

// ---- scratch (static __device__ globals: the sanctioned no-alloc scratch) ----
__device__ float g_Ts[NN * NE];            // 50.3 MB: scaled T (reused for both layers)
__device__ float g_adjAv[NN * NN];         // 16.8 MB
__device__ float g_adjAe[NE * NE];         // 151 MB
__device__ float g_HW[NN * DVO];
__device__ float g_HeW[NE * DEO];
__device__ float g_HeWs[NE * DEO];         // HeW scaled by 1/colmax
__device__ float g_de[NE];
__device__ float g_dv[NN];
__device__ float g_pmax[32 * NE];

// ---- packed f32x2 helpers (Blackwell FFMA2: 2x fp32 FMA per instruction) ----
__device__ __forceinline__ u64 pk2(float lo, float hi) {
    u64 r; asm("mov.b64 %0, {%1, %2};" : "=l"(r) : "f"(lo), "f"(hi)); return r;
}
__device__ __forceinline__ void fma2(u64 &d, u64 a, u64 b) {
    asm("fma.rn.f32x2 %0, %1, %2, %0;" : "+l"(d) : "l"(a), "l"(b));
}
__device__ __forceinline__ float2 up2(u64 v) {
    float2 f; asm("mov.b64 {%0, %1}, %2;" : "=f"(f.x), "=f"(f.y) : "l"(v)); return f;
}

// =====================  tiny prologue kernels  =====================

// d_e[e] = dot(H_e[e,:16], p_v)
__global__ void k_de(const float* __restrict__ He, const float* __restrict__ pv) {
    int e = blockIdx.x * 256 + threadIdx.x;
    float s = 0.f;
#pragma unroll
    for (int k = 0; k < DEI; k++) s += He[e * DEI + k] * pv[k];
    g_de[e] = s;
}

// HeW = H_e @ W_e  (6144x16 @ 16x16)
__global__ void k_hew(const float* __restrict__ He, const float* __restrict__ We) {
    int idx = blockIdx.x * 256 + threadIdx.x;   // 98304 total
    int e = idx >> 4, c = idx & 15;
    float s = 0.f;
#pragma unroll
    for (int k = 0; k < DEI; k++) s += He[e * DEI + k] * We[k * DEO + c];
    g_HeW[idx] = s;
}

// HW = H_v @ W_v  (2048x128 @ 128x64)
__global__ void k_hw(const float* __restrict__ Hv, const float* __restrict__ Wv) {
    int idx = blockIdx.x * 256 + threadIdx.x;   // 131072 total
    int i = idx >> 6, c = idx & 63;
    float s = 0.f;
#pragma unroll 8
    for (int k = 0; k < KDV; k++) s += Hv[i * KDV + k] * Wv[k * DVO + c];
    g_HW[idx] = s;
}

// Ts[i,k] = T[i,k] * d_e[k]   (column-scale)
__global__ void k_scale1(const float* __restrict__ T) {
    int col = blockIdx.x * 256 + threadIdx.x;
    int row = blockIdx.y;
    g_Ts[row * NE + col] = T[row * NE + col] * g_de[col];
}

// Ts[i,k] = T[i,k] * d_v[i]   (row-scale)
__global__ void k_scale2(const float* __restrict__ T) {
    int col = blockIdx.x * 256 + threadIdx.x;
    int row = blockIdx.y;
    g_Ts[row * NE + col] = T[row * NE + col] * g_dv[row];
}

// =====================  big GEMM 1: adjAv = epi(Ts @ T^T)  =====================
// M=N=2048, K=6144. A,B row-major [rows][K]. Epilogue: diag->1, * adj_v.
__global__ __launch_bounds__(256, 2) void k_mult1(const float* __restrict__ B,
                                                  const float* __restrict__ adj) {
    __shared__ __align__(16) float As[16 * 128];
    __shared__ __align__(16) float Bs[16 * 128];
    const int tid = threadIdx.x;
    const int tx = tid & 15, ty = tid >> 4;
    const int m0 = blockIdx.y * 128, n0 = blockIdx.x * 128;
    const int lrow = tid >> 2;              // 0..63
    const int lc4 = (tid & 3) * 4;          // 0,4,8,12
    const float* Ag = g_Ts + (m0 + lrow) * NE + lc4;
    const float* Bg = B + (n0 + lrow) * NE + lc4;

    u64 acc[8][4];
#pragma unroll
    for (int i = 0; i < 8; i++)
#pragma unroll
        for (int j = 0; j < 4; j++) acc[i][j] = 0ull;

    float4 pa0, pa1, pb0, pb1;
    // prologue: tile 0
    pa0 = *(const float4*)(Ag);
    pa1 = *(const float4*)(Ag + 64 * NE);
    pb0 = *(const float4*)(Bg);
    pb1 = *(const float4*)(Bg + 64 * NE);
    As[(lc4 + 0) * 128 + lrow] = pa0.x; As[(lc4 + 1) * 128 + lrow] = pa0.y;
    As[(lc4 + 2) * 128 + lrow] = pa0.z; As[(lc4 + 3) * 128 + lrow] = pa0.w;
    As[(lc4 + 0) * 128 + lrow + 64] = pa1.x; As[(lc4 + 1) * 128 + lrow + 64] = pa1.y;
    As[(lc4 + 2) * 128 + lrow + 64] = pa1.z; As[(lc4 + 3) * 128 + lrow + 64] = pa1.w;
    Bs[(lc4 + 0) * 128 + lrow] = pb0.x; Bs[(lc4 + 1) * 128 + lrow] = pb0.y;
    Bs[(lc4 + 2) * 128 + lrow] = pb0.z; Bs[(lc4 + 3) * 128 + lrow] = pb0.w;
    Bs[(lc4 + 0) * 128 + lrow + 64] = pb1.x; Bs[(lc4 + 1) * 128 + lrow + 64] = pb1.y;
    Bs[(lc4 + 2) * 128 + lrow + 64] = pb1.z; Bs[(lc4 + 3) * 128 + lrow + 64] = pb1.w;
    __syncthreads();

    for (int k0 = 0; k0 < NE; k0 += 16) {
        const int kn = k0 + 16;
        if (kn < NE) {
            pa0 = *(const float4*)(Ag + kn);
            pa1 = *(const float4*)(Ag + 64 * NE + kn);
            pb0 = *(const float4*)(Bg + kn);
            pb1 = *(const float4*)(Bg + 64 * NE + kn);
        }
#pragma unroll
        for (int kk = 0; kk < 16; kk++) {
            const float* as = As + kk * 128 + ty * 8;
            float4 a0 = *(const float4*)(as);
            float4 a1 = *(const float4*)(as + 4);
            const u64* bp = (const u64*)(Bs + kk * 128 + tx * 8);
            u64 b0 = bp[0], b1 = bp[1], b2 = bp[2], b3 = bp[3];
            float ar[8] = {a0.x, a0.y, a0.z, a0.w, a1.x, a1.y, a1.z, a1.w};
#pragma unroll
            for (int i = 0; i < 8; i++) {
                u64 a2 = pk2(ar[i], ar[i]);
                fma2(acc[i][0], a2, b0);
                fma2(acc[i][1], a2, b1);
                fma2(acc[i][2], a2, b2);
                fma2(acc[i][3], a2, b3);
            }
        }
        __syncthreads();
        if (kn < NE) {
            As[(lc4 + 0) * 128 + lrow] = pa0.x; As[(lc4 + 1) * 128 + lrow] = pa0.y;
            As[(lc4 + 2) * 128 + lrow] = pa0.z; As[(lc4 + 3) * 128 + lrow] = pa0.w;
            As[(lc4 + 0) * 128 + lrow + 64] = pa1.x; As[(lc4 + 1) * 128 + lrow + 64] = pa1.y;
            As[(lc4 + 2) * 128 + lrow + 64] = pa1.z; As[(lc4 + 3) * 128 + lrow + 64] = pa1.w;
            Bs[(lc4 + 0) * 128 + lrow] = pb0.x; Bs[(lc4 + 1) * 128 + lrow] = pb0.y;
            Bs[(lc4 + 2) * 128 + lrow] = pb0.z; Bs[(lc4 + 3) * 128 + lrow] = pb0.w;
            Bs[(lc4 + 0) * 128 + lrow + 64] = pb1.x; Bs[(lc4 + 1) * 128 + lrow + 64] = pb1.y;
            Bs[(lc4 + 2) * 128 + lrow + 64] = pb1.z; Bs[(lc4 + 3) * 128 + lrow + 64] = pb1.w;
        }
        __syncthreads();
    }

#pragma unroll
    for (int i = 0; i < 8; i++) {
        int gi = m0 + ty * 8 + i;
        int gj0 = n0 + tx * 8;
        float2 p0 = up2(acc[i][0]), p1 = up2(acc[i][1]);
        float2 p2 = up2(acc[i][2]), p3 = up2(acc[i][3]);
        float v0 = p0.x, v1 = p0.y, v2 = p1.x, v3 = p1.y;
        float v4 = p2.x, v5 = p2.y, v6 = p3.x, v7 = p3.y;
        if (gi == gj0 + 0) v0 = 1.0f;
        if (gi == gj0 + 1) v1 = 1.0f;
        if (gi == gj0 + 2) v2 = 1.0f;
        if (gi == gj0 + 3) v3 = 1.0f;
        if (gi == gj0 + 4) v4 = 1.0f;
        if (gi == gj0 + 5) v5 = 1.0f;
        if (gi == gj0 + 6) v6 = 1.0f;
        if (gi == gj0 + 7) v7 = 1.0f;
        const float4* ap = (const float4*)(adj + gi * NN + gj0);
        float4 j0 = ap[0], j1 = ap[1];
        float4* cp = (float4*)(g_adjAv + gi * NN + gj0);
        cp[0] = make_float4(v0 * j0.x, v1 * j0.y, v2 * j0.z, v3 * j0.w);
        cp[1] = make_float4(v4 * j1.x, v5 * j1.y, v6 * j1.z, v7 * j1.w);
    }
}

// =====================  big GEMM 2: adjAe = epi(Ts^T @ T)  =====================
// M=N=6144, K=2048. Operands stored [K][6144] (k-major), so tiles load naturally.
__global__ __launch_bounds__(256, 2) void k_mult2(const float* __restrict__ B,
                                                  const float* __restrict__ adj) {
    __shared__ __align__(16) float As[16 * 128];
    __shared__ __align__(16) float Bs[16 * 128];
    const int tid = threadIdx.x;
    const int tx = tid & 15, ty = tid >> 4;
    const int m0 = blockIdx.y * 128, n0 = blockIdx.x * 128;
    const int kr = tid >> 5;                // 0..7
    const int lc4 = (tid & 31) * 4;         // 0..124
    const float* Ag = g_Ts + kr * NE + m0 + lc4;
    const float* Bg = B + kr * NE + n0 + lc4;

    u64 acc[8][4];
#pragma unroll
    for (int i = 0; i < 8; i++)
#pragma unroll
        for (int j = 0; j < 4; j++) acc[i][j] = 0ull;

    float4 pa0, pa1, pb0, pb1;
    pa0 = *(const float4*)(Ag);
    pa1 = *(const float4*)(Ag + 8 * NE);
    pb0 = *(const float4*)(Bg);
    pb1 = *(const float4*)(Bg + 8 * NE);
    *(float4*)(As + kr * 128 + lc4) = pa0;
    *(float4*)(As + (kr + 8) * 128 + lc4) = pa1;
    *(float4*)(Bs + kr * 128 + lc4) = pb0;
    *(float4*)(Bs + (kr + 8) * 128 + lc4) = pb1;
    __syncthreads();

    for (int k0 = 0; k0 < NN; k0 += 16) {
        const int kn = k0 + 16;
        if (kn < NN) {
            pa0 = *(const float4*)(Ag + kn * NE);
            pa1 = *(const float4*)(Ag + (kn + 8) * NE);
            pb0 = *(const float4*)(Bg + kn * NE);
            pb1 = *(const float4*)(Bg + (kn + 8) * NE);
        }
#pragma unroll
        for (int kk = 0; kk < 16; kk++) {
            const float* as = As + kk * 128 + ty * 8;
            float4 a0 = *(const float4*)(as);
            float4 a1 = *(const float4*)(as + 4);
            const u64* bp = (const u64*)(Bs + kk * 128 + tx * 8);
            u64 b0 = bp[0], b1 = bp[1], b2 = bp[2], b3 = bp[3];
            float ar[8] = {a0.x, a0.y, a0.z, a0.w, a1.x, a1.y, a1.z, a1.w};
#pragma unroll
            for (int i = 0; i < 8; i++) {
                u64 a2 = pk2(ar[i], ar[i]);
                fma2(acc[i][0], a2, b0);
                fma2(acc[i][1], a2, b1);
                fma2(acc[i][2], a2, b2);
                fma2(acc[i][3], a2, b3);
            }
        }
        __syncthreads();
        if (kn < NN) {
            *(float4*)(As + kr * 128 + lc4) = pa0;
            *(float4*)(As + (kr + 8) * 128 + lc4) = pa1;
            *(float4*)(Bs + kr * 128 + lc4) = pb0;
            *(float4*)(Bs + (kr + 8) * 128 + lc4) = pb1;
        }
        __syncthreads();
    }

#pragma unroll
    for (int i = 0; i < 8; i++) {
        int gi = m0 + ty * 8 + i;
        int gj0 = n0 + tx * 8;
        float2 p0 = up2(acc[i][0]), p1 = up2(acc[i][1]);
        float2 p2 = up2(acc[i][2]), p3 = up2(acc[i][3]);
        float v0 = p0.x, v1 = p0.y, v2 = p1.x, v3 = p1.y;
        float v4 = p2.x, v5 = p2.y, v6 = p3.x, v7 = p3.y;
        if (gi == gj0 + 0) v0 = 1.0f;
        if (gi == gj0 + 1) v1 = 1.0f;
        if (gi == gj0 + 2) v2 = 1.0f;
        if (gi == gj0 + 3) v3 = 1.0f;
        if (gi == gj0 + 4) v4 = 1.0f;
        if (gi == gj0 + 5) v5 = 1.0f;
        if (gi == gj0 + 6) v6 = 1.0f;
        if (gi == gj0 + 7) v7 = 1.0f;
        const float4* ap = (const float4*)(adj + gi * NE + gj0);
        float4 j0 = ap[0], j1 = ap[1];
        float4* cp = (float4*)(g_adjAe + gi * NE + gj0);
        cp[0] = make_float4(v0 * j0.x, v1 * j0.y, v2 * j0.z, v3 * j0.w);
        cp[1] = make_float4(v4 * j1.x, v5 * j1.y, v6 * j1.z, v7 * j1.w);
    }
}

// =====================  Hv_out = adjAv @ HW + b_v  (2048x2048x64)  =====================
__global__ __launch_bounds__(256) void k_hv(const float* __restrict__ bv, float* __restrict__ out) {
    __shared__ __align__(16) float As[32 * 32];   // [k][m]
    __shared__ __align__(16) float Bs[32 * 64];   // [k][n]
    const int tid = threadIdx.x;
    const int tx = tid & 15, ty = tid >> 4;
    const int m0 = blockIdx.x * 32;
    const int arow = tid >> 3, ac4 = (tid & 7) * 4;
    const int brow = tid >> 4, bc4 = (tid & 15) * 4;
    float acc[2][4] = {{0, 0, 0, 0}, {0, 0, 0, 0}};
    for (int k0 = 0; k0 < NN; k0 += 32) {
        float4 fa = *(const float4*)(g_adjAv + (m0 + arow) * NN + k0 + ac4);
        float4 fb0 = *(const float4*)(g_HW + (k0 + brow) * DVO + bc4);
        float4 fb1 = *(const float4*)(g_HW + (k0 + brow + 16) * DVO + bc4);
        __syncthreads();
        As[(ac4 + 0) * 32 + arow] = fa.x; As[(ac4 + 1) * 32 + arow] = fa.y;
        As[(ac4 + 2) * 32 + arow] = fa.z; As[(ac4 + 3) * 32 + arow] = fa.w;
        *(float4*)(Bs + brow * 64 + bc4) = fb0;
        *(float4*)(Bs + (brow + 16) * 64 + bc4) = fb1;
        __syncthreads();
#pragma unroll
        for (int kk = 0; kk < 32; kk++) {
            float a0 = As[kk * 32 + ty * 2];
            float a1 = As[kk * 32 + ty * 2 + 1];
            float4 b = *(const float4*)(Bs + kk * 64 + tx * 4);
            acc[0][0] += a0 * b.x; acc[0][1] += a0 * b.y; acc[0][2] += a0 * b.z; acc[0][3] += a0 * b.w;
            acc[1][0] += a1 * b.x; acc[1][1] += a1 * b.y; acc[1][2] += a1 * b.z; acc[1][3] += a1 * b.w;
        }
    }
    float4 bb = *(const float4*)(bv + tx * 4);
#pragma unroll
    for (int r = 0; r < 2; r++) {
        int row = m0 + ty * 2 + r;
        *(float4*)(out + row * DVO + tx * 4) =
            make_float4(acc[r][0] + bb.x, acc[r][1] + bb.y, acc[r][2] + bb.z, acc[r][3] + bb.w);
    }
}

// d_v[i] = dot(Hv_out[i,:64], p_e)
__global__ void k_dv(const float* __restrict__ Hv, const float* __restrict__ pe) {
    int w = (blockIdx.x * blockDim.x + threadIdx.x) >> 5;
    int lane = threadIdx.x & 31;
    float s = Hv[w * DVO + lane] * pe[lane] + Hv[w * DVO + 32 + lane] * pe[32 + lane];
#pragma unroll
    for (int o = 16; o > 0; o >>= 1) s += __shfl_down_sync(0xffffffffu, s, o);
    if (lane == 0) g_dv[w] = s;
}

// column-max of adjAe, stage 1 (partial over 192-row chunks)
__global__ void k_cmax1() {
    int col = blockIdx.x * 256 + threadIdx.x;
    int r0 = blockIdx.y * 192;
    float m = -3.402823466e38f;
#pragma unroll 4
    for (int r = 0; r < 192; r++) m = fmaxf(m, g_adjAe[(r0 + r) * NE + col]);
    g_pmax[blockIdx.y * NE + col] = m;
}

// stage 2: finalize colmax, fold 1/(max+1e-10) into HeW -> HeWs
__global__ void k_cmax2() {
    int col = blockIdx.x * 256 + threadIdx.x;
    float m = -3.402823466e38f;
#pragma unroll
    for (int y = 0; y < 32; y++) m = fmaxf(m, g_pmax[y * NE + col]);
    float inv = 1.0f / (m + 1e-10f);
#pragma unroll
    for (int c = 0; c < DEO; c++) g_HeWs[col * DEO + c] = g_HeW[col * DEO + c] * inv;
}

// He_out = adjAe @ HeWs + b_e   (6144x6144x16)
__global__ __launch_bounds__(256) void k_he(const float* __restrict__ be, float* __restrict__ out) {
    __shared__ __align__(16) float As[64 * 64];
    __shared__ __align__(16) float Bs[64 * 16];
    const int tid = threadIdx.x;
    const int c = tid & 15, tr = tid >> 4;
    const int m0 = blockIdx.x * 64;
    const int lc4 = (tid & 15) * 4;
    float acc[4] = {0, 0, 0, 0};
    for (int k0 = 0; k0 < NE; k0 += 64) {
        float4 ra[4]; float rb[4];
#pragma unroll
        for (int q = 0; q < 4; q++) {
            int row = tr + q * 16;
            ra[q] = *(const float4*)(g_adjAe + (m0 + row) * NE + k0 + lc4);
            rb[q] = g_HeWs[(k0 + row) * DEO + c];
        }
        __syncthreads();
#pragma unroll
        for (int q = 0; q < 4; q++) {
            int row = tr + q * 16;
            *(float4*)(As + row * 64 + lc4) = ra[q];
            Bs[row * 16 + c] = rb[q];
        }
        __syncthreads();
#pragma unroll 8
        for (int kk = 0; kk < 64; kk++) {
            float b = Bs[kk * 16 + c];
            acc[0] += As[(0 * 16 + tr) * 64 + kk] * b;
            acc[1] += As[(1 * 16 + tr) * 64 + kk] * b;
            acc[2] += As[(2 * 16 + tr) * 64 + kk] * b;
            acc[3] += As[(3 * 16 + tr) * 64 + kk] * b;
        }
    }
    float bc = be[c];
#pragma unroll
    for (int q = 0; q < 4; q++)
        out[(m0 + q * 16 + tr) * DEO + c] = acc[q] + bc;
}

// =====================  launch  =====================
extern "C" void kernel_launch(void* const* d_in, const int* in_sizes, int n_in,
                              void* d_out, int out_size) {
    const float* H_v  = (const float*)d_in[0];
    const float* H_e  = (const float*)d_in[1];
    const float* adjv = (const float*)d_in[2];
    const float* adje = (const float*)d_in[3];
    const float* T    = (const float*)d_in[4];
    const float* W_v  = (const float*)d_in[5];
    const float* b_v  = (const float*)d_in[6];
    const float* p_v  = (const float*)d_in[7];
    const float* W_e  = (const float*)d_in[8];
    const float* b_e  = (const float*)d_in[9];
    const float* p_e  = (const float*)d_in[10];
    float* out = (float*)d_out;

    (void)in_sizes; (void)n_in; (void)out_size;

    k_de<<<24, 256>>>(H_e, p_v);                         // d_e
    k_hew<<<384, 256>>>(H_e, W_e);                       // H_e @ W_e
    k_hw<<<512, 256>>>(H_v, W_v);                        // H_v @ W_v
    k_scale1<<<dim3(24, 2048), 256>>>(T);                // Ts = T * d_e (cols)
    k_mult1<<<dim3(16, 16), 256>>>(T, adjv);             // adjAv (fused diag + *adj_v)
    k_hv<<<64, 256>>>(b_v, out);                         // Hv_out -> d_out[0:131072]
    k_dv<<<256, 256>>>(out, p_e);                        // d_v
    k_scale2<<<dim3(24, 2048), 256>>>(T);                // Ts = T * d_v (rows)
    k_mult2<<<dim3(48, 48), 256>>>(T, adje);             // adjAe (fused diag + *adj_e)
    k_cmax1<<<dim3(24, 32), 256>>>();                    // partial column max
    k_cmax2<<<24, 256>>>();                              // colmax -> scale HeW
    k_he<<<96, 256>>>(b_e, out + NN * DVO);              // He_out -> d_out[131072:]
}

// round 3
// speedup vs baseline: 2.1448x; 2.1448x over previous
#include <cuda_runtime.h>
#include <cuda_bf16.h>
#include <cstdint>

typedef unsigned int u32;
typedef unsigned long long u64;
typedef __nv_bfloat16 bf16;

#define NN 2048
#define NE 6144
#define KDV 128
#define DVO 64
#define DEI 16
#define DEO 16

// =====================  scratch  =====================
__device__ __align__(16) bf16 g_m1A_hi[NN * NE];
__device__ __align__(16) bf16 g_m1A_lo[NN * NE];
__device__ __align__(16) bf16 g_m1B_hi[NN * NE];
__device__ __align__(16) bf16 g_m1B_lo[NN * NE];
__device__ __align__(16) bf16 g_m2A_hi[NE * NN];
__device__ __align__(16) bf16 g_m2A_lo[NE * NN];
__device__ __align__(16) bf16 g_m2B_hi[NE * NN];
__device__ __align__(16) bf16 g_m2B_lo[NE * NN];
__device__ __align__(16) float g_adjAv[NN * NN];
__device__ __align__(16) float g_adjAe[(size_t)NE * NE];
__device__ __align__(16) float g_HW[NN * DVO];
__device__ __align__(16) float g_HeW[NE * DEO];
__device__ __align__(16) float g_HeWs[NE * DEO];
__device__ __align__(16) float g_de[NE];
__device__ __align__(16) float g_dv[NN];
__device__ __align__(16) float g_pmax[32 * NE];

// =====================  helpers  =====================
__device__ __forceinline__ u32 smem_u32(const void* p) {
    u32 a;
    asm("{ .reg .u64 t; cvta.to.shared.u64 t, %1; cvt.u32.u64 %0, t; }" : "=r"(a) : "l"(p));
    return a;
}

__device__ __forceinline__ void cp16(u32 saddr, const bf16* gptr) {
    asm volatile("cp.async.cg.shared.global [%0], [%1], 16;"
                 :: "r"(saddr), "l"(__cvta_generic_to_global(gptr)) : "memory");
}

#define LDSM4(r, addr)                                                          \
    asm volatile("ldmatrix.sync.aligned.m8n8.x4.shared.b16 {%0,%1,%2,%3}, [%4];" \
                 : "=r"((r)[0]), "=r"((r)[1]), "=r"((r)[2]), "=r"((r)[3]) : "r"(addr))

#define MMA_BF16(d, a, b)                                                        \
    asm volatile("mma.sync.aligned.m16n8k16.row.col.f32.bf16.bf16.f32 "          \
                 "{%0,%1,%2,%3},{%4,%5,%6,%7},{%8,%9},{%0,%1,%2,%3};"            \
                 : "+f"((d)[0]), "+f"((d)[1]), "+f"((d)[2]), "+f"((d)[3])        \
                 : "r"((a)[0]), "r"((a)[1]), "r"((a)[2]), "r"((a)[3]),           \
                   "r"((b)[0]), "r"((b)[1]))

// bf16 split: hi = rn(x), lo = rn(x - hi)
__device__ __forceinline__ void bsplit(float x, bf16& hi, bf16& lo) {
    hi = __float2bfloat16_rn(x);
    lo = __float2bfloat16_rn(x - __bfloat162float(hi));
}
__device__ __forceinline__ u32 pkb2(bf16 a, bf16 b) {
    __nv_bfloat162 h = __halves2bfloat162(a, b);
    return *(u32*)&h;
}

// =====================  tiny prologue kernels  =====================
__global__ void k_de(const float* __restrict__ He, const float* __restrict__ pv) {
    int e = blockIdx.x * 256 + threadIdx.x;
    float s = 0.f;
#pragma unroll
    for (int k = 0; k < DEI; k++) s += He[e * DEI + k] * pv[k];
    g_de[e] = s;
}

__global__ void k_hew(const float* __restrict__ He, const float* __restrict__ We) {
    int idx = blockIdx.x * 256 + threadIdx.x;
    int e = idx >> 4, c = idx & 15;
    float s = 0.f;
#pragma unroll
    for (int k = 0; k < DEI; k++) s += He[e * DEI + k] * We[k * DEO + c];
    g_HeW[idx] = s;
}

__global__ void k_hw(const float* __restrict__ Hv, const float* __restrict__ Wv) {
    int idx = blockIdx.x * 256 + threadIdx.x;
    int i = idx >> 6, c = idx & 63;
    float s = 0.f;
#pragma unroll 8
    for (int k = 0; k < KDV; k++) s += Hv[i * KDV + k] * Wv[k * DVO + c];
    g_HW[idx] = s;
}

// mult1 prep: B = T (hi/lo), A = T * d_e[col] (hi/lo). [NN][NE] K-major, bf16.
__global__ void k_split1(const float* __restrict__ T) {
    size_t i = (size_t)blockIdx.x * 256 + threadIdx.x;   // float4 index
    float4 t = ((const float4*)T)[i];
    int col = (int)((i * 4) % NE);
    float4 de = *(const float4*)(g_de + col);
    bf16 hx, lx, hy, ly, hz, lz, hw, lw;
    bsplit(t.x, hx, lx); bsplit(t.y, hy, ly); bsplit(t.z, hz, lz); bsplit(t.w, hw, lw);
    ((uint2*)g_m1B_hi)[i] = make_uint2(pkb2(hx, hy), pkb2(hz, hw));
    ((uint2*)g_m1B_lo)[i] = make_uint2(pkb2(lx, ly), pkb2(lz, lw));
    float ax = t.x * de.x, ay = t.y * de.y, az = t.z * de.z, aw = t.w * de.w;
    bsplit(ax, hx, lx); bsplit(ay, hy, ly); bsplit(az, hz, lz); bsplit(aw, hw, lw);
    ((uint2*)g_m1A_hi)[i] = make_uint2(pkb2(hx, hy), pkb2(hz, hw));
    ((uint2*)g_m1A_lo)[i] = make_uint2(pkb2(lx, ly), pkb2(lz, lw));
}

// mult2 prep (transpose): B2[m][k] = T[k][m]; A2[m][k] = T[k][m]*d_v[k]. [NE][NN] bf16.
__global__ void k_split2(const float* __restrict__ T) {
    __shared__ float tile[32][33];
    int m0 = blockIdx.x * 32, k0 = blockIdx.y * 32;
    int tx = threadIdx.x, ty = threadIdx.y;
#pragma unroll
    for (int j = 0; j < 4; j++)
        tile[ty + j * 8][tx] = T[(size_t)(k0 + ty + j * 8) * NE + m0 + tx];
    __syncthreads();
    float dv = g_dv[k0 + tx];
#pragma unroll
    for (int j = 0; j < 4; j++) {
        int m = m0 + ty + j * 8;
        float v = tile[tx][ty + j * 8];
        size_t o = (size_t)m * NN + k0 + tx;
        bf16 hi, lo;
        bsplit(v, hi, lo);
        g_m2B_hi[o] = hi; g_m2B_lo[o] = lo;
        bsplit(v * dv, hi, lo);
        g_m2A_hi[o] = hi; g_m2A_lo[o] = lo;
    }
}

// =====================  bf16 3-term tensor-core GEMM + fused epilogue  =====================
// C[m][n] = epi( sum_k A[m][k]*B[n][k] ), CTA tile 128x128, warp 64x32, KB=64, 3-stage cp.async.
#define KB 64
#define STG_BYTES 65536          // Ahi 16K | Alo 16K | Bhi 16K | Blo 16K
#define NSTAGE 3
#define SMEM_DYN (NSTAGE * STG_BYTES)

__device__ __forceinline__ void stage_load(u32 st0, int s,
        const bf16* __restrict__ Ahi, const bf16* __restrict__ Alo,
        const bf16* __restrict__ Bhi, const bf16* __restrict__ Blo,
        int K, int m0, int n0, int k0, int tid) {
    u32 base = st0 + s * STG_BYTES;
#pragma unroll
    for (int i = 0; i < 4; i++) {
        int id = tid + i * 256;
        int r = id >> 3, c = id & 7;
        u32 so = (u32)(r * 128 + (((c ^ (r & 7))) << 4));
        size_t gA = (size_t)(m0 + r) * K + k0 + c * 8;
        size_t gB = (size_t)(n0 + r) * K + k0 + c * 8;
        cp16(base + so, Ahi + gA);
        cp16(base + 16384 + so, Alo + gA);
        cp16(base + 32768 + so, Bhi + gB);
        cp16(base + 49152 + so, Blo + gB);
    }
    asm volatile("cp.async.commit_group;" ::: "memory");
}

__global__ __launch_bounds__(256, 1) void k_mult_mma(int which, const float* __restrict__ adj) {
    extern __shared__ char smem[];
    const bf16 *Ahi, *Alo, *Bhi, *Blo;
    float* C;
    int K, ncols;
    if (which == 0) {
        Ahi = g_m1A_hi; Alo = g_m1A_lo; Bhi = g_m1B_hi; Blo = g_m1B_lo;
        C = g_adjAv; K = NE; ncols = NN;
    } else {
        Ahi = g_m2A_hi; Alo = g_m2A_lo; Bhi = g_m2B_hi; Blo = g_m2B_lo;
        C = g_adjAe; K = NN; ncols = NE;
    }
    const u32 st0 = smem_u32(smem);
    const int tid = threadIdx.x;
    const int lane = tid & 31, wid = tid >> 5;
    const int wm = wid >> 2, wn = wid & 3;          // 2 x 4 warp grid
    const int m0 = blockIdx.y * 128, n0 = blockIdx.x * 128;
    const int nk = K / KB;

    float acc[4][4][4];
#pragma unroll
    for (int i = 0; i < 4; i++)
#pragma unroll
        for (int j = 0; j < 4; j++)
#pragma unroll
            for (int q = 0; q < 4; q++) acc[i][j][q] = 0.f;

    stage_load(st0, 0, Ahi, Alo, Bhi, Blo, K, m0, n0, 0, tid);
    stage_load(st0, 1, Ahi, Alo, Bhi, Blo, K, m0, n0, KB, tid);

    const u32 arow = (u32)(wm * 64 + (lane & 15));
    const u32 brow = (u32)(wn * 32 + (lane & 15));
    const u32 asw = arow & 7, bsw = brow & 7;

    for (int kt = 0; kt < nk; kt++) {
        const int s = kt % NSTAGE;
        asm volatile("cp.async.wait_group 1;" ::: "memory");
        __syncthreads();
        if (kt + 2 < nk)
            stage_load(st0, (kt + 2) % NSTAGE, Ahi, Alo, Bhi, Blo, K, m0, n0, (kt + 2) * KB, tid);

        const u32 base = st0 + s * STG_BYTES;
#pragma unroll
        for (int ks = 0; ks < 4; ks++) {
            const u32 cb = (u32)(ks * 2) + (u32)(lane >> 4);
            u32 Ah[4][4], Al[4][4], Bh[4][2], Bl[4][2];
            const u32 aoff = base + arow * 128 + ((cb ^ asw) << 4);
#pragma unroll
            for (int mi = 0; mi < 4; mi++) {
                LDSM4(Ah[mi], aoff + mi * 2048);
                LDSM4(Al[mi], aoff + 16384 + mi * 2048);
            }
            const u32 boff = base + 32768 + brow * 128 + ((cb ^ bsw) << 4);
#pragma unroll
            for (int nip = 0; nip < 2; nip++) {
                u32 t[4];
                LDSM4(t, boff + nip * 2048);
                Bh[2 * nip][0] = t[0]; Bh[2 * nip][1] = t[2];
                Bh[2 * nip + 1][0] = t[1]; Bh[2 * nip + 1][1] = t[3];
                LDSM4(t, boff + 16384 + nip * 2048);
                Bl[2 * nip][0] = t[0]; Bl[2 * nip][1] = t[2];
                Bl[2 * nip + 1][0] = t[1]; Bl[2 * nip + 1][1] = t[3];
            }
#pragma unroll
            for (int mi = 0; mi < 4; mi++)
#pragma unroll
                for (int ni = 0; ni < 4; ni++) {
                    MMA_BF16(acc[mi][ni], Ah[mi], Bh[ni]);
                    MMA_BF16(acc[mi][ni], Ah[mi], Bl[ni]);
                    MMA_BF16(acc[mi][ni], Al[mi], Bh[ni]);
                }
        }
        __syncthreads();
    }

    // epilogue: diag -> 1, * adj, store
#pragma unroll
    for (int mi = 0; mi < 4; mi++) {
#pragma unroll
        for (int h = 0; h < 2; h++) {
            const int row_g = m0 + wm * 64 + mi * 16 + (lane >> 2) + h * 8;
            const size_t rb = (size_t)row_g * ncols;
#pragma unroll
            for (int ni = 0; ni < 4; ni++) {
                const int col_g = n0 + wn * 32 + ni * 8 + (lane & 3) * 2;
                float v0 = acc[mi][ni][h * 2], v1 = acc[mi][ni][h * 2 + 1];
                if (row_g == col_g) v0 = 1.0f;
                if (row_g == col_g + 1) v1 = 1.0f;
                const float2 a = *(const float2*)(adj + rb + col_g);
                *(float2*)(C + rb + col_g) = make_float2(v0 * a.x, v1 * a.y);
            }
        }
    }
}

// =====================  Hv_out = adjAv @ HW + b_v  =====================
__global__ __launch_bounds__(256) void k_hv(const float* __restrict__ bv, float* __restrict__ out) {
    __shared__ __align__(16) float As[32 * 32];
    __shared__ __align__(16) float Bs[32 * 64];
    const int tid = threadIdx.x;
    const int tx = tid & 15, ty = tid >> 4;
    const int m0 = blockIdx.x * 32;
    const int arow = tid >> 3, ac4 = (tid & 7) * 4;
    const int brow = tid >> 4, bc4 = (tid & 15) * 4;
    float acc[2][4] = {{0, 0, 0, 0}, {0, 0, 0, 0}};
    for (int k0 = 0; k0 < NN; k0 += 32) {
        float4 fa = *(const float4*)(g_adjAv + (m0 + arow) * NN + k0 + ac4);
        float4 fb0 = *(const float4*)(g_HW + (k0 + brow) * DVO + bc4);
        float4 fb1 = *(const float4*)(g_HW + (k0 + brow + 16) * DVO + bc4);
        __syncthreads();
        As[(ac4 + 0) * 32 + arow] = fa.x; As[(ac4 + 1) * 32 + arow] = fa.y;
        As[(ac4 + 2) * 32 + arow] = fa.z; As[(ac4 + 3) * 32 + arow] = fa.w;
        *(float4*)(Bs + brow * 64 + bc4) = fb0;
        *(float4*)(Bs + (brow + 16) * 64 + bc4) = fb1;
        __syncthreads();
#pragma unroll
        for (int kk = 0; kk < 32; kk++) {
            float a0 = As[kk * 32 + ty * 2];
            float a1 = As[kk * 32 + ty * 2 + 1];
            float4 b = *(const float4*)(Bs + kk * 64 + tx * 4);
            acc[0][0] += a0 * b.x; acc[0][1] += a0 * b.y; acc[0][2] += a0 * b.z; acc[0][3] += a0 * b.w;
            acc[1][0] += a1 * b.x; acc[1][1] += a1 * b.y; acc[1][2] += a1 * b.z; acc[1][3] += a1 * b.w;
        }
    }
    float4 bb = *(const float4*)(bv + tx * 4);
#pragma unroll
    for (int r = 0; r < 2; r++) {
        int row = m0 + ty * 2 + r;
        *(float4*)(out + row * DVO + tx * 4) =
            make_float4(acc[r][0] + bb.x, acc[r][1] + bb.y, acc[r][2] + bb.z, acc[r][3] + bb.w);
    }
}

__global__ void k_dv(const float* __restrict__ Hv, const float* __restrict__ pe) {
    int w = (blockIdx.x * blockDim.x + threadIdx.x) >> 5;
    int lane = threadIdx.x & 31;
    float s = Hv[w * DVO + lane] * pe[lane] + Hv[w * DVO + 32 + lane] * pe[32 + lane];
#pragma unroll
    for (int o = 16; o > 0; o >>= 1) s += __shfl_down_sync(0xffffffffu, s, o);
    if (lane == 0) g_dv[w] = s;
}

__global__ void k_cmax1() {
    int col = blockIdx.x * 256 + threadIdx.x;
    int r0 = blockIdx.y * 192;
    float m = -3.402823466e38f;
#pragma unroll 4
    for (int r = 0; r < 192; r++) m = fmaxf(m, g_adjAe[(size_t)(r0 + r) * NE + col]);
    g_pmax[blockIdx.y * NE + col] = m;
}

__global__ void k_cmax2() {
    int col = blockIdx.x * 256 + threadIdx.x;
    float m = -3.402823466e38f;
#pragma unroll
    for (int y = 0; y < 32; y++) m = fmaxf(m, g_pmax[y * NE + col]);
    float inv = 1.0f / (m + 1e-10f);
#pragma unroll
    for (int c = 0; c < DEO; c++) g_HeWs[col * DEO + c] = g_HeW[col * DEO + c] * inv;
}

__global__ __launch_bounds__(256) void k_he(const float* __restrict__ be, float* __restrict__ out) {
    __shared__ __align__(16) float As[64 * 64];
    __shared__ __align__(16) float Bs[64 * 16];
    const int tid = threadIdx.x;
    const int c = tid & 15, tr = tid >> 4;
    const int m0 = blockIdx.x * 64;
    const int lc4 = (tid & 15) * 4;
    float acc[4] = {0, 0, 0, 0};
    for (int k0 = 0; k0 < NE; k0 += 64) {
        float4 ra[4]; float rb[4];
#pragma unroll
        for (int q = 0; q < 4; q++) {
            int row = tr + q * 16;
            ra[q] = *(const float4*)(g_adjAe + (size_t)(m0 + row) * NE + k0 + lc4);
            rb[q] = g_HeWs[(k0 + row) * DEO + c];
        }
        __syncthreads();
#pragma unroll
        for (int q = 0; q < 4; q++) {
            int row = tr + q * 16;
            *(float4*)(As + row * 64 + lc4) = ra[q];
            Bs[row * 16 + c] = rb[q];
        }
        __syncthreads();
#pragma unroll 8
        for (int kk = 0; kk < 64; kk++) {
            float b = Bs[kk * 16 + c];
            acc[0] += As[(0 * 16 + tr) * 64 + kk] * b;
            acc[1] += As[(1 * 16 + tr) * 64 + kk] * b;
            acc[2] += As[(2 * 16 + tr) * 64 + kk] * b;
            acc[3] += As[(3 * 16 + tr) * 64 + kk] * b;
        }
    }
    float bc = be[c];
#pragma unroll
    for (int q = 0; q < 4; q++)
        out[(m0 + q * 16 + tr) * DEO + c] = acc[q] + bc;
}

// =====================  launch  =====================
extern "C" void kernel_launch(void* const* d_in, const int* in_sizes, int n_in,
                              void* d_out, int out_size) {
    const float* H_v  = (const float*)d_in[0];
    const float* H_e  = (const float*)d_in[1];
    const float* adjv = (const float*)d_in[2];
    const float* adje = (const float*)d_in[3];
    const float* T    = (const float*)d_in[4];
    const float* W_v  = (const float*)d_in[5];
    const float* b_v  = (const float*)d_in[6];
    const float* p_v  = (const float*)d_in[7];
    const float* W_e  = (const float*)d_in[8];
    const float* b_e  = (const float*)d_in[9];
    const float* p_e  = (const float*)d_in[10];
    float* out = (float*)d_out;
    (void)in_sizes; (void)n_in; (void)out_size;

    static int smem_set = 0;
    if (!smem_set) {
        cudaFuncSetAttribute(k_mult_mma, cudaFuncAttributeMaxDynamicSharedMemorySize, SMEM_DYN);
        smem_set = 1;
    }

    k_de<<<24, 256>>>(H_e, p_v);
    k_hew<<<384, 256>>>(H_e, W_e);
    k_hw<<<512, 256>>>(H_v, W_v);
    k_split1<<<12288, 256>>>(T);
    k_mult_mma<<<dim3(16, 16), 256, SMEM_DYN>>>(0, adjv);   // adjAv
    k_hv<<<64, 256>>>(b_v, out);
    k_dv<<<256, 256>>>(out, p_e);
    k_split2<<<dim3(192, 64), dim3(32, 8)>>>(T);
    k_mult_mma<<<dim3(48, 48), 256, SMEM_DYN>>>(1, adje);   // adjAe
    k_cmax1<<<dim3(24, 32), 256>>>();
    k_cmax2<<<24, 256>>>();
    k_he<<<96, 256>>>(b_e, out + NN * DVO);
}